// round 1
// baseline (speedup 1.0000x reference)
#include <cuda_runtime.h>
#include <math.h>

// ---------------- problem dims (fixed) ----------------
#define NB   2      // batch
#define LT   512    // txt tokens
#define NI   2048   // img tokens (H=64, W=32)
#define DM   512    // model dim
#define NHD  4      // heads
#define HDD  128    // head dim
#define FFD  2048   // mlp hidden
#define KVL  2560   // LT + NI
#define E6   3072   // 6*DM adaln embedding
#define SCALE_C 0.08838834764831845f  // 128^-0.5

// ---------------- scratch (__device__ globals; allocation-free) ----------------
__device__ __align__(256) float d_e_img[NB*E6];
__device__ __align__(256) float d_e_txt[NB*E6];
__device__ __align__(256) float d_eff[NB];
__device__ __align__(256) float d_mod[NB*NHD*NI];
__device__ __align__(256) float d_nimg[NB*NI*DM];
__device__ __align__(256) float d_ntxt[NB*LT*DM];
__device__ __align__(256) float d_qkvi[NB*NI*3*NHD*HDD];
__device__ __align__(256) float d_qkvt[NB*LT*3*NHD*HDD];
__device__ __align__(256) float d_Qi[NB*NHD*NI*HDD];
__device__ __align__(256) float d_Qt[NB*NHD*LT*HDD];
__device__ __align__(256) float d_Kc[NB*NHD*KVL*HDD];
__device__ __align__(256) float d_VT[NB*NHD*HDD*KVL];
__device__ __align__(256) float d_St[NB*NHD*LT*KVL];
__device__ __align__(256) float d_Si[NB*NHD*NI*KVL];
__device__ __align__(256) float d_att_t[NB*NHD*LT*HDD];
__device__ __align__(256) float d_att_i[NB*NHD*NI*HDD];
__device__ __align__(256) float d_apt[NB*LT*DM];
__device__ __align__(256) float d_api[NB*NI*DM];
__device__ __align__(256) float d_prt[NB*LT*DM];
__device__ __align__(256) float d_pri[NB*NI*DM];
__device__ __align__(256) float d_ct[NB*LT*DM];
__device__ __align__(256) float d_ci[NB*NI*DM];
__device__ __align__(256) float d_ht[NB*LT*FFD];
__device__ __align__(256) float d_hi[NB*NI*FFD];

// ---------------- reductions ----------------
__device__ __forceinline__ float warpSum(float v){
  #pragma unroll
  for (int o=16;o>0;o>>=1) v += __shfl_xor_sync(0xffffffffu, v, o);
  return v;
}
__device__ __forceinline__ float warpMax(float v){
  #pragma unroll
  for (int o=16;o>0;o>>=1) v = fmaxf(v, __shfl_xor_sync(0xffffffffu, v, o));
  return v;
}

// ---------------- generic batched SGEMM: C = alpha * A(MxK) @ B(NxK)^T ----------------
__global__ __launch_bounds__(256) void sgemm_abt(
    const float* __restrict__ A, const float* __restrict__ Bm,
    float* __restrict__ C, int M, int N, int K,
    long long sA, long long sB, long long sC,
    float alpha, const float* __restrict__ alphas, int alpha_div)
{
  A  += (long long)blockIdx.z * sA;
  Bm += (long long)blockIdx.z * sB;
  C  += (long long)blockIdx.z * sC;
  float alp = alphas ? alphas[blockIdx.z / alpha_div] : alpha;

  __shared__ float As[8][128];
  __shared__ float Bs[8][128];

  int tid = threadIdx.x;
  int bm = blockIdx.y * 128;
  int bn = blockIdx.x * 128;
  int lr = tid >> 1;
  int lc = (tid & 1) * 4;
  int tx = tid & 15;
  int ty = tid >> 4;

  const float* Ald = A  + (long long)(bm + lr) * K + lc;
  const float* Bld = Bm + (long long)(bn + lr) * K + lc;

  float acc[8][8];
  #pragma unroll
  for (int i=0;i<8;i++)
    #pragma unroll
    for (int j=0;j<8;j++) acc[i][j]=0.f;

  for (int k0 = 0; k0 < K; k0 += 8) {
    float4 av = *(const float4*)(Ald + k0);
    float4 bv = *(const float4*)(Bld + k0);
    As[lc+0][lr]=av.x; As[lc+1][lr]=av.y; As[lc+2][lr]=av.z; As[lc+3][lr]=av.w;
    Bs[lc+0][lr]=bv.x; Bs[lc+1][lr]=bv.y; Bs[lc+2][lr]=bv.z; Bs[lc+3][lr]=bv.w;
    __syncthreads();
    #pragma unroll
    for (int kk = 0; kk < 8; kk++) {
      float4 a0 = *(const float4*)&As[kk][ty*8];
      float4 a1 = *(const float4*)&As[kk][ty*8+4];
      float4 b0 = *(const float4*)&Bs[kk][tx*8];
      float4 b1 = *(const float4*)&Bs[kk][tx*8+4];
      float af[8] = {a0.x,a0.y,a0.z,a0.w,a1.x,a1.y,a1.z,a1.w};
      float bf[8] = {b0.x,b0.y,b0.z,b0.w,b1.x,b1.y,b1.z,b1.w};
      #pragma unroll
      for (int i=0;i<8;i++)
        #pragma unroll
        for (int j=0;j<8;j++)
          acc[i][j] += af[i]*bf[j];
    }
    __syncthreads();
  }
  #pragma unroll
  for (int i=0;i<8;i++){
    float* cp = C + (long long)(bm + ty*8 + i)*N + bn + tx*8;
    float4 v0 = make_float4(acc[i][0]*alp, acc[i][1]*alp, acc[i][2]*alp, acc[i][3]*alp);
    float4 v1 = make_float4(acc[i][4]*alp, acc[i][5]*alp, acc[i][6]*alp, acc[i][7]*alp);
    *(float4*)cp = v0;
    *(float4*)(cp+4) = v1;
  }
}

// ---------------- adaln embedding: e = silu(vec) @ W^T + b ----------------
__global__ void k_emb(const float* __restrict__ vec, const float* __restrict__ W,
                      const float* __restrict__ bias, float* __restrict__ e)
{
  int b = blockIdx.y;
  __shared__ float s[DM];
  for (int i = threadIdx.x; i < DM; i += blockDim.x){
    float v = vec[b*DM + i];
    s[i] = v / (1.f + expf(-v));
  }
  __syncthreads();
  int n = blockIdx.x*blockDim.x + threadIdx.x;
  const float* wr = W + (long long)n*DM;
  float acc = 0.f;
  #pragma unroll 8
  for (int k = 0; k < DM; k++) acc += s[k]*wr[k];
  e[b*E6 + n] = acc + bias[n];
}

// ---------------- eff = SCALE / max(mean(temp), 0.1) ----------------
__global__ void k_eff(const float* __restrict__ t, float* __restrict__ eff){
  int b = threadIdx.x;
  if (b < NB){
    float m = 0.25f*(t[b*NHD+0]+t[b*NHD+1]+t[b*NHD+2]+t[b*NHD+3]);
    eff[b] = SCALE_C / fmaxf(m, 0.1f);
  }
}

// ---------------- mod[b,h,n] = exp(clip(bilerp(sol_spatial) * w[h] + b[h], -2, 2)) ----------------
__global__ void k_mod(const float* __restrict__ sp, const float* __restrict__ mw,
                      const float* __restrict__ mb, float* __restrict__ mod)
{
  int idx = blockIdx.x*blockDim.x + threadIdx.x;
  if (idx >= NB*NHD*NI) return;
  int n = idx & (NI-1);
  int h = (idx >> 11) & (NHD-1);
  int b = idx >> 13;
  int y = n >> 5;          // W = 32
  int x = n & 31;
  float fy = (y + 0.5f)*0.125f - 0.5f;   // 64 <- 8
  float fx = (x + 0.5f)*0.25f  - 0.5f;   // 32 <- 8
  int y0 = (int)floorf(fy); float wy = fy - (float)y0;
  int x0 = (int)floorf(fx); float wx = fx - (float)x0;
  int y0c = min(max(y0,0),7), y1c = min(max(y0+1,0),7);
  int x0c = min(max(x0,0),7), x1c = min(max(x0+1,0),7);
  const float* p = sp + b*64;
  float v = (1.f-wy)*((1.f-wx)*p[y0c*8+x0c] + wx*p[y0c*8+x1c])
          +      wy *((1.f-wx)*p[y1c*8+x0c] + wx*p[y1c*8+x1c]);
  v = v*mw[h] + mb[h];
  v = fminf(fmaxf(v, -2.f), 2.f);
  mod[idx] = expf(v);
}

// ---------------- rms-norm + adaln modulate: out = rms(x)*w*(1+e[scale]) + e[shift] ----------------
__global__ __launch_bounds__(128) void k_rmsmod(
    const float* __restrict__ x, const float* __restrict__ w,
    const float* __restrict__ e, int shift_off, int scale_off,
    float* __restrict__ out, int tok_per_b)
{
  int row = blockIdx.x;
  int b = row / tok_per_b;
  float4 xv = ((const float4*)(x + (long long)row*DM))[threadIdx.x];
  float ss = xv.x*xv.x + xv.y*xv.y + xv.z*xv.z + xv.w*xv.w;
  ss = warpSum(ss);
  __shared__ float red[4];
  int lane = threadIdx.x & 31, wid = threadIdx.x >> 5;
  if (lane==0) red[wid]=ss;
  __syncthreads();
  float tot = red[0]+red[1]+red[2]+red[3];
  float inv = rsqrtf(tot*(1.f/DM) + 1e-6f);
  int c = threadIdx.x*4;
  const float* eb = e + b*E6;
  float4 o;
  o.x = xv.x*inv*w[c+0]*(1.f+eb[scale_off+c+0]) + eb[shift_off+c+0];
  o.y = xv.y*inv*w[c+1]*(1.f+eb[scale_off+c+1]) + eb[shift_off+c+1];
  o.z = xv.z*inv*w[c+2]*(1.f+eb[scale_off+c+2]) + eb[shift_off+c+2];
  o.w = xv.w*inv*w[c+3]*(1.f+eb[scale_off+c+3]) + eb[shift_off+c+3];
  ((float4*)(out + (long long)row*DM))[threadIdx.x] = o;
}

// ---------------- scatter img qkv: rope + mod, build Q, K(+512 offset), V^T ----------------
__global__ void k_scatter_img(const float* __restrict__ qkv, const float* __restrict__ rope,
                              const float* __restrict__ mod,
                              float* __restrict__ Q, float* __restrict__ K,
                              float* __restrict__ VT)
{
  int idx = blockIdx.x*blockDim.x + threadIdx.x;   // NB*NHD*NI*64
  int d2 = idx & 63;
  int r  = idx >> 6;            // bh*NI + n
  int n  = r & (NI-1);
  int bh = r >> 11;
  int h  = bh & (NHD-1);
  int b  = bh >> 2;
  const float* base = qkv + ((long long)(b*NI + n))*(3*NHD*HDD) + h*HDD + 2*d2;
  float2 q = *(const float2*)(base);
  float2 k = *(const float2*)(base + NHD*HDD);
  float2 v = *(const float2*)(base + 2*NHD*HDD);
  float c = rope[n*HDD + 2*d2];
  float s = rope[n*HDD + 2*d2 + 1];
  float m = mod[r];
  float q0 = (q.x*c - q.y*s)*m, q1 = (q.y*c + q.x*s)*m;
  float k0 = (k.x*c - k.y*s)*m, k1 = (k.y*c + k.x*s)*m;
  *(float2*)(Q + (long long)r*HDD + 2*d2) = make_float2(q0,q1);
  long long kv = (long long)bh*KVL + (LT + n);
  *(float2*)(K + kv*HDD + 2*d2) = make_float2(k0,k1);
  VT[((long long)bh*HDD + 2*d2  )*KVL + (LT+n)] = v.x;
  VT[((long long)bh*HDD + 2*d2+1)*KVL + (LT+n)] = v.y;
}

// ---------------- scatter txt qkv: build Q, K(offset 0), V^T ----------------
__global__ void k_scatter_txt(const float* __restrict__ qkv,
                              float* __restrict__ Q, float* __restrict__ K,
                              float* __restrict__ VT)
{
  int idx = blockIdx.x*blockDim.x + threadIdx.x;   // NB*NHD*LT*64
  int d2 = idx & 63;
  int r  = idx >> 6;            // bh*LT + l
  int l  = r & (LT-1);
  int bh = r >> 9;
  int h  = bh & (NHD-1);
  int b  = bh >> 2;
  const float* base = qkv + ((long long)(b*LT + l))*(3*NHD*HDD) + h*HDD + 2*d2;
  float2 q = *(const float2*)(base);
  float2 k = *(const float2*)(base + NHD*HDD);
  float2 v = *(const float2*)(base + 2*NHD*HDD);
  *(float2*)(Q + (long long)r*HDD + 2*d2) = q;
  long long kv = (long long)bh*KVL + l;
  *(float2*)(K + kv*HDD + 2*d2) = k;
  VT[((long long)bh*HDD + 2*d2  )*KVL + l] = v.x;
  VT[((long long)bh*HDD + 2*d2+1)*KVL + l] = v.y;
}

// ---------------- softmax over rows of length KVL=2560 (256 threads, 10 elems each) ----------------
__global__ __launch_bounds__(256) void k_softmax(float* __restrict__ S){
  long long row = blockIdx.x;
  float* p = S + row*KVL;
  int tid = threadIdx.x;
  float v[10];
  float m = -1e30f;
  #pragma unroll
  for (int i=0;i<10;i++){ v[i] = p[tid + i*256]; m = fmaxf(m, v[i]); }
  m = warpMax(m);
  __shared__ float redm[8];
  __shared__ float reds[8];
  int lane = tid & 31, wid = tid >> 5;
  if (lane==0) redm[wid]=m;
  __syncthreads();
  float bm = redm[0];
  #pragma unroll
  for (int i=1;i<8;i++) bm = fmaxf(bm, redm[i]);
  float sum = 0.f;
  #pragma unroll
  for (int i=0;i<10;i++){ v[i] = __expf(v[i]-bm); sum += v[i]; }
  sum = warpSum(sum);
  if (lane==0) reds[wid]=sum;
  __syncthreads();
  float tot = reds[0]+reds[1]+reds[2]+reds[3]+reds[4]+reds[5]+reds[6]+reds[7];
  float inv = 1.f/tot;
  #pragma unroll
  for (int i=0;i<10;i++) p[tid + i*256] = v[i]*inv;
}

// ---------------- pack [b,h,t,d] -> [b,t,h*HD+d] ----------------
__global__ void k_pack(const float* __restrict__ att, float* __restrict__ out, int T){
  int idx = blockIdx.x*blockDim.x + threadIdx.x;
  if (idx >= NB*T*DM) return;
  int c = idx & (DM-1);
  int rowt = idx >> 9;
  int t = rowt % T;
  int b = rowt / T;
  int h = c >> 7;
  int d = c & (HDD-1);
  out[idx] = att[(((long long)(b*NHD+h)*T + t)*HDD) + d];
}

// ---------------- out = res + e[b, off + d] * x ----------------
__global__ void k_resgate(const float* __restrict__ res, const float* __restrict__ x,
                          const float* __restrict__ e, int off,
                          float* __restrict__ out, int T)
{
  int idx = blockIdx.x*blockDim.x + threadIdx.x;
  if (idx >= NB*T*DM) return;
  int d = idx & (DM-1);
  int b = (idx >> 9) / T;
  out[idx] = res[idx] + e[b*E6 + off + d]*x[idx];
}

// ---------------- h = gelu_tanh(h + bias) ----------------
__global__ void k_biasgelu(float* __restrict__ h, const float* __restrict__ bias, int total){
  int idx = blockIdx.x*blockDim.x + threadIdx.x;
  if (idx >= total) return;
  float x = h[idx] + bias[idx & (FFD-1)];
  float x3 = x*x*x;
  float t = tanhf(0.7978845608028654f*(x + 0.044715f*x3));
  h[idx] = 0.5f*x*(1.f+t);
}

// ---------------- out = cur + e[b, 2560 + d]*(x + bias[d]) ----------------
__global__ void k_final(const float* __restrict__ cur, const float* __restrict__ x,
                        const float* __restrict__ e, const float* __restrict__ bias,
                        float* __restrict__ out, int T)
{
  int idx = blockIdx.x*blockDim.x + threadIdx.x;
  if (idx >= NB*T*DM) return;
  int d = idx & (DM-1);
  int b = (idx >> 9) / T;
  out[idx] = cur[idx] + e[b*E6 + 2560 + d]*(x[idx] + bias[d]);
}

// ---------------- launch ----------------
#define GETSYM(var, sym) float* var; cudaGetSymbolAddress((void**)&var, sym)

extern "C" void kernel_launch(void* const* d_in, const int* in_sizes, int n_in,
                              void* d_out, int out_size)
{
  const float* txt          = (const float*)d_in[0];
  const float* img          = (const float*)d_in[1];
  const float* vec          = (const float*)d_in[2];
  const float* rope         = (const float*)d_in[3];
  const float* sol_t        = (const float*)d_in[4];
  const float* sol_s        = (const float*)d_in[5];
  const float* img_adaln_w  = (const float*)d_in[6];
  const float* img_adaln_b  = (const float*)d_in[7];
  const float* img_adaln_nw = (const float*)d_in[8];
  const float* txt_adaln_w  = (const float*)d_in[9];
  const float* txt_adaln_b  = (const float*)d_in[10];
  const float* txt_adaln_nw = (const float*)d_in[11];
  const float* txt_qkv_w    = (const float*)d_in[12];
  const float* img_qkv_w    = (const float*)d_in[13];
  const float* txt_out_w    = (const float*)d_in[14];
  const float* img_out_w    = (const float*)d_in[15];
  const float* sol_mod_w    = (const float*)d_in[16];
  const float* sol_mod_b    = (const float*)d_in[17];
  const float* img_norm2_w  = (const float*)d_in[18];
  const float* txt_norm2_w  = (const float*)d_in[19];
  const float* img_fc1_w    = (const float*)d_in[20];
  const float* img_fc1_b    = (const float*)d_in[21];
  const float* img_fc2_w    = (const float*)d_in[22];
  const float* img_fc2_b    = (const float*)d_in[23];
  const float* txt_fc1_w    = (const float*)d_in[24];
  const float* txt_fc1_b    = (const float*)d_in[25];
  const float* txt_fc2_w    = (const float*)d_in[26];
  const float* txt_fc2_b    = (const float*)d_in[27];
  float* out = (float*)d_out;

  GETSYM(e_img, d_e_img);  GETSYM(e_txt, d_e_txt);
  GETSYM(eff, d_eff);      GETSYM(mod, d_mod);
  GETSYM(nimg, d_nimg);    GETSYM(ntxt, d_ntxt);
  GETSYM(qkvi, d_qkvi);    GETSYM(qkvt, d_qkvt);
  GETSYM(Qi, d_Qi);        GETSYM(Qt, d_Qt);
  GETSYM(Kc, d_Kc);        GETSYM(VT, d_VT);
  GETSYM(St, d_St);        GETSYM(Si, d_Si);
  GETSYM(att_t, d_att_t);  GETSYM(att_i, d_att_i);
  GETSYM(apt, d_apt);      GETSYM(api, d_api);
  GETSYM(prt, d_prt);      GETSYM(pri, d_pri);
  GETSYM(ct, d_ct);        GETSYM(ci, d_ci);
  GETSYM(ht, d_ht);        GETSYM(hi, d_hi);

  // 1. adaln embeddings
  k_emb<<<dim3(E6/256, NB), 256>>>(vec, img_adaln_w, img_adaln_b, e_img);
  k_emb<<<dim3(E6/256, NB), 256>>>(vec, txt_adaln_w, txt_adaln_b, e_txt);
  // 2. eff + mod
  k_eff<<<1, 32>>>(sol_t, eff);
  k_mod<<<(NB*NHD*NI)/256, 256>>>(sol_s, sol_mod_w, sol_mod_b, mod);
  // 3. norm1 (shift=sm@0, scale=cm@512)
  k_rmsmod<<<NB*NI, 128>>>(img, img_adaln_nw, e_img, 0, 512, nimg, NI);
  k_rmsmod<<<NB*LT, 128>>>(txt, txt_adaln_nw, e_txt, 0, 512, ntxt, LT);
  // 4. qkv projections
  sgemm_abt<<<dim3(12, 32, 1), 256>>>(nimg, img_qkv_w, qkvi, NB*NI, 1536, DM, 0,0,0, 1.f, nullptr, 1);
  sgemm_abt<<<dim3(12,  8, 1), 256>>>(ntxt, txt_qkv_w, qkvt, NB*LT, 1536, DM, 0,0,0, 1.f, nullptr, 1);
  // 5. scatter -> Q, K, V^T (rope + mod on img)
  k_scatter_img<<<(NB*NHD*NI*64)/256, 256>>>(qkvi, rope, mod, Qi, Kc, VT);
  k_scatter_txt<<<(NB*NHD*LT*64)/256, 256>>>(qkvt, Qt, Kc, VT);
  // 6. scores: S = alpha * Q @ K^T, batched over 8 (b,h)
  sgemm_abt<<<dim3(KVL/128, LT/128, NB*NHD), 256>>>(Qt, Kc, St, LT, KVL, HDD,
      (long long)LT*HDD, (long long)KVL*HDD, (long long)LT*KVL, SCALE_C, nullptr, 1);
  sgemm_abt<<<dim3(KVL/128, NI/128, NB*NHD), 256>>>(Qi, Kc, Si, NI, KVL, HDD,
      (long long)NI*HDD, (long long)KVL*HDD, (long long)NI*KVL, 1.f, eff, NHD);
  // 7. softmax
  k_softmax<<<NB*NHD*LT, 256>>>(St);
  k_softmax<<<NB*NHD*NI, 256>>>(Si);
  // 8. P @ V  (V stored transposed -> fits A@B^T)
  sgemm_abt<<<dim3(1, LT/128, NB*NHD), 256>>>(St, VT, att_t, LT, HDD, KVL,
      (long long)LT*KVL, (long long)HDD*KVL, (long long)LT*HDD, 1.f, nullptr, 1);
  sgemm_abt<<<dim3(1, NI/128, NB*NHD), 256>>>(Si, VT, att_i, NI, HDD, KVL,
      (long long)NI*KVL, (long long)HDD*KVL, (long long)NI*HDD, 1.f, nullptr, 1);
  // 9. pack heads
  k_pack<<<(NB*LT*DM)/256, 256>>>(att_t, apt, LT);
  k_pack<<<(NB*NI*DM)/256, 256>>>(att_i, api, NI);
  // 10. output projections
  sgemm_abt<<<dim3(4,  8, 1), 256>>>(apt, txt_out_w, prt, NB*LT, DM, DM, 0,0,0, 1.f, nullptr, 1);
  sgemm_abt<<<dim3(4, 32, 1), 256>>>(api, img_out_w, pri, NB*NI, DM, DM, 0,0,0, 1.f, nullptr, 1);
  // 11. attention residual with gate gm@1024
  k_resgate<<<(NB*LT*DM)/256, 256>>>(txt, prt, e_txt, 1024, ct, LT);
  k_resgate<<<(NB*NI*DM)/256, 256>>>(img, pri, e_img, 1024, ci, NI);
  // 12. norm2 (shift=sp@1536, scale=cp@2048)
  k_rmsmod<<<NB*LT, 128>>>(ct, txt_norm2_w, e_txt, 1536, 2048, ntxt, LT);
  k_rmsmod<<<NB*NI, 128>>>(ci, img_norm2_w, e_img, 1536, 2048, nimg, NI);
  // 13. mlp fc1
  sgemm_abt<<<dim3(16,  8, 1), 256>>>(ntxt, txt_fc1_w, ht, NB*LT, FFD, DM, 0,0,0, 1.f, nullptr, 1);
  sgemm_abt<<<dim3(16, 32, 1), 256>>>(nimg, img_fc1_w, hi, NB*NI, FFD, DM, 0,0,0, 1.f, nullptr, 1);
  // 14. bias + gelu
  k_biasgelu<<<(NB*LT*FFD)/256, 256>>>(ht, txt_fc1_b, NB*LT*FFD);
  k_biasgelu<<<(NB*NI*FFD)/256, 256>>>(hi, img_fc1_b, NB*NI*FFD);
  // 15. mlp fc2 (reuse proj buffers)
  sgemm_abt<<<dim3(4,  8, 1), 256>>>(ht, txt_fc2_w, prt, NB*LT, DM, FFD, 0,0,0, 1.f, nullptr, 1);
  sgemm_abt<<<dim3(4, 32, 1), 256>>>(hi, img_fc2_w, pri, NB*NI, DM, FFD, 0,0,0, 1.f, nullptr, 1);
  // 16. final residual with gate gp@2560 (+fc2 bias) -> d_out (txt first, then img)
  k_final<<<(NB*LT*DM)/256, 256>>>(ct, prt, e_txt, txt_fc2_b, out, LT);
  k_final<<<(NB*NI*DM)/256, 256>>>(ci, pri, e_img, img_fc2_b, out + NB*LT*DM, NI);
}

// round 3
// speedup vs baseline: 2.4502x; 2.4502x over previous
#include <cuda_runtime.h>
#include <math.h>
#include <stdint.h>

// ---------------- problem dims (fixed) ----------------
#define NB   2      // batch
#define LT   512    // txt tokens
#define NI   2048   // img tokens (H=64, W=32)
#define DM   512    // model dim
#define NHD  4      // heads
#define HDD  128    // head dim
#define FFD  2048   // mlp hidden
#define KVL  2560   // LT + NI
#define E6   3072   // 6*DM adaln embedding
#define SCALE_C 0.08838834764831845f  // 128^-0.5

// ---------------- scratch (__device__ globals; allocation-free) ----------------
__device__ __align__(256) float d_e_img[NB*E6];
__device__ __align__(256) float d_e_txt[NB*E6];
__device__ __align__(256) float d_eff[NB];
__device__ __align__(256) float d_mod[NB*NHD*NI];
__device__ __align__(256) float d_nimg[NB*NI*DM];
__device__ __align__(256) float d_ntxt[NB*LT*DM];
__device__ __align__(256) float d_qkvi[NB*NI*3*NHD*HDD];
__device__ __align__(256) float d_qkvt[NB*LT*3*NHD*HDD];
__device__ __align__(256) float d_Qi[NB*NHD*NI*HDD];
__device__ __align__(256) float d_Qt[NB*NHD*LT*HDD];
__device__ __align__(256) float d_Kc[NB*NHD*KVL*HDD];
__device__ __align__(256) float d_VT[NB*NHD*HDD*KVL];
__device__ __align__(256) float d_St[NB*NHD*LT*KVL];
__device__ __align__(256) float d_Si[NB*NHD*NI*KVL];
__device__ __align__(256) float d_att_t[NB*NHD*LT*HDD];
__device__ __align__(256) float d_att_i[NB*NHD*NI*HDD];
__device__ __align__(256) float d_apt[NB*LT*DM];
__device__ __align__(256) float d_api[NB*NI*DM];
__device__ __align__(256) float d_prt[NB*LT*DM];
__device__ __align__(256) float d_pri[NB*NI*DM];
__device__ __align__(256) float d_ct[NB*LT*DM];
__device__ __align__(256) float d_ci[NB*NI*DM];
__device__ __align__(256) float d_ht[NB*LT*FFD];
__device__ __align__(256) float d_hi[NB*NI*FFD];

// ---------------- helpers ----------------
__device__ __forceinline__ float warpSum(float v){
  #pragma unroll
  for (int o=16;o>0;o>>=1) v += __shfl_xor_sync(0xffffffffu, v, o);
  return v;
}
__device__ __forceinline__ float warpMax(float v){
  #pragma unroll
  for (int o=16;o>0;o>>=1) v = fmaxf(v, __shfl_xor_sync(0xffffffffu, v, o));
  return v;
}
__device__ __forceinline__ uint32_t sptr(const void* p){
  uint32_t r;
  asm("{ .reg .u64 t; cvta.to.shared.u64 t, %1; cvt.u32.u64 %0, t; }" : "=r"(r) : "l"(p));
  return r;
}
__device__ __forceinline__ uint32_t f2tf32(float x){
  uint32_t r;
  asm("cvt.rna.tf32.f32 %0, %1;" : "=r"(r) : "f"(x));
  return r;
}

// ================= tf32 mma.sync batched GEMM: C = alpha * A(MxK) @ B(NxK)^T =================
// CTA tile 128x128, 8 warps (2x4), warp tile 64x32, K-chunk 32, double-buffered cp.async.
#define TSTRIDE 36                 // padded row stride (floats), conflict-free
#define STAGE_F (128*TSTRIDE)      // floats per matrix per stage
#define TG_DSMEM (4*STAGE_F*4)     // 2 stages x (A+B) x 4B = 73728

__global__ __launch_bounds__(256) void tgemm(
    const float* __restrict__ A, const float* __restrict__ Bm,
    float* __restrict__ C, int N, int K,
    long long sA, long long sB, long long sC,
    float alpha, const float* __restrict__ alphas, int adiv)
{
  extern __shared__ float smem[];
  float* As = smem;                // [2][STAGE_F]
  float* Bs = smem + 2*STAGE_F;    // [2][STAGE_F]

  const int tid = threadIdx.x;
  const int z   = blockIdx.z;
  const long long bm = (long long)blockIdx.y * 128;
  const long long bn = (long long)blockIdx.x * 128;

  const float* Ab = A  + z*sA + bm*K;
  const float* Bb = Bm + z*sB + bn*K;
  float alp = alphas ? alphas[z/adiv] : alpha;

  const int lw  = tid & 31;
  const int w   = tid >> 5;
  const int wr  = (w >> 2) * 64;   // warp row base in tile
  const int wc  = (w & 3) * 32;    // warp col base in tile
  const int g   = lw >> 2;         // group id 0..7
  const int tg  = lw & 3;          // thread in group 0..3

  // loader mapping: row = tid>>1 (0..127), 16 floats starting at (tid&1)*16
  const int lrow = tid >> 1;
  const int lcol = (tid & 1) * 16;

  float acc[4][4][4];
  #pragma unroll
  for (int i=0;i<4;i++)
    #pragma unroll
    for (int j=0;j<4;j++)
      #pragma unroll
      for (int q=0;q<4;q++) acc[i][j][q] = 0.f;

  const int nch = K >> 5;

  auto load_chunk = [&](int c, int st){
    const float* Ag = Ab + (long long)lrow*K + c*32 + lcol;
    const float* Bg = Bb + (long long)lrow*K + c*32 + lcol;
    uint32_t da = sptr(As + st*STAGE_F + lrow*TSTRIDE + lcol);
    uint32_t db = sptr(Bs + st*STAGE_F + lrow*TSTRIDE + lcol);
    #pragma unroll
    for (int j = 0; j < 4; j++){
      asm volatile("cp.async.cg.shared.global [%0], [%1], 16;" :: "r"(da + j*16), "l"(Ag + j*4));
      asm volatile("cp.async.cg.shared.global [%0], [%1], 16;" :: "r"(db + j*16), "l"(Bg + j*4));
    }
    asm volatile("cp.async.commit_group;");
  };

  load_chunk(0, 0);

  for (int i = 0; i < nch; i++){
    int st = i & 1;
    if (i + 1 < nch){
      load_chunk(i+1, st^1);
      asm volatile("cp.async.wait_group 1;" ::: "memory");
    } else {
      asm volatile("cp.async.wait_group 0;" ::: "memory");
    }
    __syncthreads();

    const float* Ast = As + st*STAGE_F;
    const float* Bst = Bs + st*STAGE_F;

    #pragma unroll
    for (int ks = 0; ks < 4; ks++){
      int kb = ks*8;
      uint32_t af[4][4];
      #pragma unroll
      for (int mt = 0; mt < 4; mt++){
        const float* ap = Ast + (wr + mt*16 + g)*TSTRIDE + kb + tg;
        af[mt][0] = f2tf32(ap[0]);
        af[mt][1] = f2tf32(ap[8*TSTRIDE]);
        af[mt][2] = f2tf32(ap[4]);
        af[mt][3] = f2tf32(ap[8*TSTRIDE + 4]);
      }
      uint32_t bf[4][2];
      #pragma unroll
      for (int nt = 0; nt < 4; nt++){
        const float* bp = Bst + (wc + nt*8 + g)*TSTRIDE + kb + tg;
        bf[nt][0] = f2tf32(bp[0]);
        bf[nt][1] = f2tf32(bp[4]);
      }
      #pragma unroll
      for (int mt = 0; mt < 4; mt++)
        #pragma unroll
        for (int nt = 0; nt < 4; nt++){
          asm volatile(
            "mma.sync.aligned.m16n8k8.row.col.f32.tf32.tf32.f32 "
            "{%0,%1,%2,%3}, {%4,%5,%6,%7}, {%8,%9}, {%0,%1,%2,%3};"
            : "+f"(acc[mt][nt][0]), "+f"(acc[mt][nt][1]),
              "+f"(acc[mt][nt][2]), "+f"(acc[mt][nt][3])
            : "r"(af[mt][0]), "r"(af[mt][1]), "r"(af[mt][2]), "r"(af[mt][3]),
              "r"(bf[nt][0]), "r"(bf[nt][1]));
        }
    }
    __syncthreads();
  }

  // epilogue
  float* Cb = C + z*sC;
  #pragma unroll
  for (int mt = 0; mt < 4; mt++){
    long long r0 = bm + wr + mt*16 + g;
    #pragma unroll
    for (int nt = 0; nt < 4; nt++){
      long long c0 = bn + wc + nt*8 + 2*tg;
      float2 v0 = make_float2(acc[mt][nt][0]*alp, acc[mt][nt][1]*alp);
      float2 v1 = make_float2(acc[mt][nt][2]*alp, acc[mt][nt][3]*alp);
      *(float2*)(Cb + r0*N + c0)     = v0;
      *(float2*)(Cb + (r0+8)*N + c0) = v1;
    }
  }
}

// ---------------- adaln embedding: e = silu(vec) @ W^T + b ----------------
__global__ void k_emb(const float* __restrict__ vec, const float* __restrict__ W,
                      const float* __restrict__ bias, float* __restrict__ e)
{
  int b = blockIdx.y;
  __shared__ float s[DM];
  for (int i = threadIdx.x; i < DM; i += blockDim.x){
    float v = vec[b*DM + i];
    s[i] = v / (1.f + expf(-v));
  }
  __syncthreads();
  int n = blockIdx.x*blockDim.x + threadIdx.x;
  const float* wr = W + (long long)n*DM;
  float acc = 0.f;
  #pragma unroll 8
  for (int k = 0; k < DM; k++) acc += s[k]*wr[k];
  e[b*E6 + n] = acc + bias[n];
}

// ---------------- eff = SCALE / max(mean(temp), 0.1) ----------------
__global__ void k_eff(const float* __restrict__ t, float* __restrict__ eff){
  int b = threadIdx.x;
  if (b < NB){
    float m = 0.25f*(t[b*NHD+0]+t[b*NHD+1]+t[b*NHD+2]+t[b*NHD+3]);
    eff[b] = SCALE_C / fmaxf(m, 0.1f);
  }
}

// ---------------- mod[b,h,n] = exp(clip(bilerp(sol_spatial) * w[h] + b[h], -2, 2)) ----------------
__global__ void k_mod(const float* __restrict__ sp, const float* __restrict__ mw,
                      const float* __restrict__ mb, float* __restrict__ mod)
{
  int idx = blockIdx.x*blockDim.x + threadIdx.x;
  if (idx >= NB*NHD*NI) return;
  int n = idx & (NI-1);
  int h = (idx >> 11) & (NHD-1);
  int b = idx >> 13;
  int y = n >> 5;          // W = 32
  int x = n & 31;
  float fy = (y + 0.5f)*0.125f - 0.5f;   // 64 <- 8
  float fx = (x + 0.5f)*0.25f  - 0.5f;   // 32 <- 8
  int y0 = (int)floorf(fy); float wy = fy - (float)y0;
  int x0 = (int)floorf(fx); float wx = fx - (float)x0;
  int y0c = min(max(y0,0),7), y1c = min(max(y0+1,0),7);
  int x0c = min(max(x0,0),7), x1c = min(max(x0+1,0),7);
  const float* p = sp + b*64;
  float v = (1.f-wy)*((1.f-wx)*p[y0c*8+x0c] + wx*p[y0c*8+x1c])
          +      wy *((1.f-wx)*p[y1c*8+x0c] + wx*p[y1c*8+x1c]);
  v = v*mw[h] + mb[h];
  v = fminf(fmaxf(v, -2.f), 2.f);
  mod[idx] = expf(v);
}

// ---------------- rms-norm + adaln modulate ----------------
__global__ __launch_bounds__(128) void k_rmsmod(
    const float* __restrict__ x, const float* __restrict__ w,
    const float* __restrict__ e, int shift_off, int scale_off,
    float* __restrict__ out, int tok_per_b)
{
  int row = blockIdx.x;
  int b = row / tok_per_b;
  float4 xv = ((const float4*)(x + (long long)row*DM))[threadIdx.x];
  float ss = xv.x*xv.x + xv.y*xv.y + xv.z*xv.z + xv.w*xv.w;
  ss = warpSum(ss);
  __shared__ float red[4];
  int lane = threadIdx.x & 31, wid = threadIdx.x >> 5;
  if (lane==0) red[wid]=ss;
  __syncthreads();
  float tot = red[0]+red[1]+red[2]+red[3];
  float inv = rsqrtf(tot*(1.f/DM) + 1e-6f);
  int c = threadIdx.x*4;
  const float* eb = e + b*E6;
  float4 o;
  o.x = xv.x*inv*w[c+0]*(1.f+eb[scale_off+c+0]) + eb[shift_off+c+0];
  o.y = xv.y*inv*w[c+1]*(1.f+eb[scale_off+c+1]) + eb[shift_off+c+1];
  o.z = xv.z*inv*w[c+2]*(1.f+eb[scale_off+c+2]) + eb[shift_off+c+2];
  o.w = xv.w*inv*w[c+3]*(1.f+eb[scale_off+c+3]) + eb[shift_off+c+3];
  ((float4*)(out + (long long)row*DM))[threadIdx.x] = o;
}

// ---------------- scatter img qkv: rope + mod, build Q, K(+512 offset), V^T ----------------
__global__ void k_scatter_img(const float* __restrict__ qkv, const float* __restrict__ rope,
                              const float* __restrict__ mod,
                              float* __restrict__ Q, float* __restrict__ K,
                              float* __restrict__ VT)
{
  int idx = blockIdx.x*blockDim.x + threadIdx.x;   // NB*NHD*NI*64
  int d2 = idx & 63;
  int r  = idx >> 6;            // bh*NI + n
  int n  = r & (NI-1);
  int bh = r >> 11;
  int h  = bh & (NHD-1);
  int b  = bh >> 2;
  const float* base = qkv + ((long long)(b*NI + n))*(3*NHD*HDD) + h*HDD + 2*d2;
  float2 q = *(const float2*)(base);
  float2 k = *(const float2*)(base + NHD*HDD);
  float2 v = *(const float2*)(base + 2*NHD*HDD);
  float c = rope[n*HDD + 2*d2];
  float s = rope[n*HDD + 2*d2 + 1];
  float m = mod[r];
  float q0 = (q.x*c - q.y*s)*m, q1 = (q.y*c + q.x*s)*m;
  float k0 = (k.x*c - k.y*s)*m, k1 = (k.y*c + k.x*s)*m;
  *(float2*)(Q + (long long)r*HDD + 2*d2) = make_float2(q0,q1);
  long long kv = (long long)bh*KVL + (LT + n);
  *(float2*)(K + kv*HDD + 2*d2) = make_float2(k0,k1);
  VT[((long long)bh*HDD + 2*d2  )*KVL + (LT+n)] = v.x;
  VT[((long long)bh*HDD + 2*d2+1)*KVL + (LT+n)] = v.y;
}

// ---------------- scatter txt qkv ----------------
__global__ void k_scatter_txt(const float* __restrict__ qkv,
                              float* __restrict__ Q, float* __restrict__ K,
                              float* __restrict__ VT)
{
  int idx = blockIdx.x*blockDim.x + threadIdx.x;   // NB*NHD*LT*64
  int d2 = idx & 63;
  int r  = idx >> 6;            // bh*LT + l
  int l  = r & (LT-1);
  int bh = r >> 9;
  int h  = bh & (NHD-1);
  int b  = bh >> 2;
  const float* base = qkv + ((long long)(b*LT + l))*(3*NHD*HDD) + h*HDD + 2*d2;
  float2 q = *(const float2*)(base);
  float2 k = *(const float2*)(base + NHD*HDD);
  float2 v = *(const float2*)(base + 2*NHD*HDD);
  *(float2*)(Q + (long long)r*HDD + 2*d2) = q;
  long long kv = (long long)bh*KVL + l;
  *(float2*)(K + kv*HDD + 2*d2) = k;
  VT[((long long)bh*HDD + 2*d2  )*KVL + l] = v.x;
  VT[((long long)bh*HDD + 2*d2+1)*KVL + l] = v.y;
}

// ---------------- softmax over rows of length KVL ----------------
__global__ __launch_bounds__(256) void k_softmax(float* __restrict__ S){
  long long row = blockIdx.x;
  float* p = S + row*KVL;
  int tid = threadIdx.x;
  float v[10];
  float m = -1e30f;
  #pragma unroll
  for (int i=0;i<10;i++){ v[i] = p[tid + i*256]; m = fmaxf(m, v[i]); }
  m = warpMax(m);
  __shared__ float redm[8];
  __shared__ float reds[8];
  int lane = tid & 31, wid = tid >> 5;
  if (lane==0) redm[wid]=m;
  __syncthreads();
  float bm = redm[0];
  #pragma unroll
  for (int i=1;i<8;i++) bm = fmaxf(bm, redm[i]);
  float sum = 0.f;
  #pragma unroll
  for (int i=0;i<10;i++){ v[i] = __expf(v[i]-bm); sum += v[i]; }
  sum = warpSum(sum);
  if (lane==0) reds[wid]=sum;
  __syncthreads();
  float tot = reds[0]+reds[1]+reds[2]+reds[3]+reds[4]+reds[5]+reds[6]+reds[7];
  float inv = 1.f/tot;
  #pragma unroll
  for (int i=0;i<10;i++) p[tid + i*256] = v[i]*inv;
}

// ---------------- pack [b,h,t,d] -> [b,t,h*HD+d] ----------------
__global__ void k_pack(const float* __restrict__ att, float* __restrict__ out, int T){
  int idx = blockIdx.x*blockDim.x + threadIdx.x;
  if (idx >= NB*T*DM) return;
  int c = idx & (DM-1);
  int rowt = idx >> 9;
  int t = rowt % T;
  int b = rowt / T;
  int h = c >> 7;
  int d = c & (HDD-1);
  out[idx] = att[(((long long)(b*NHD+h)*T + t)*HDD) + d];
}

// ---------------- out = res + e[b, off + d] * x ----------------
__global__ void k_resgate(const float* __restrict__ res, const float* __restrict__ x,
                          const float* __restrict__ e, int off,
                          float* __restrict__ out, int T)
{
  int idx = blockIdx.x*blockDim.x + threadIdx.x;
  if (idx >= NB*T*DM) return;
  int d = idx & (DM-1);
  int b = (idx >> 9) / T;
  out[idx] = res[idx] + e[b*E6 + off + d]*x[idx];
}

// ---------------- h = gelu_tanh(h + bias) ----------------
__global__ void k_biasgelu(float* __restrict__ h, const float* __restrict__ bias, int total){
  int idx = blockIdx.x*blockDim.x + threadIdx.x;
  if (idx >= total) return;
  float x = h[idx] + bias[idx & (FFD-1)];
  float x3 = x*x*x;
  float t = tanhf(0.7978845608028654f*(x + 0.044715f*x3));
  h[idx] = 0.5f*x*(1.f+t);
}

// ---------------- out = cur + e[b, 2560 + d]*(x + bias[d]) ----------------
__global__ void k_final(const float* __restrict__ cur, const float* __restrict__ x,
                        const float* __restrict__ e, const float* __restrict__ bias,
                        float* __restrict__ out, int T)
{
  int idx = blockIdx.x*blockDim.x + threadIdx.x;
  if (idx >= NB*T*DM) return;
  int d = idx & (DM-1);
  int b = (idx >> 9) / T;
  out[idx] = cur[idx] + e[b*E6 + 2560 + d]*(x[idx] + bias[d]);
}

// ---------------- launch ----------------
#define GETSYM(var, sym) float* var; cudaGetSymbolAddress((void**)&var, sym)

extern "C" void kernel_launch(void* const* d_in, const int* in_sizes, int n_in,
                              void* d_out, int out_size)
{
  const float* txt          = (const float*)d_in[0];
  const float* img          = (const float*)d_in[1];
  const float* vec          = (const float*)d_in[2];
  const float* rope         = (const float*)d_in[3];
  const float* sol_t        = (const float*)d_in[4];
  const float* sol_s        = (const float*)d_in[5];
  const float* img_adaln_w  = (const float*)d_in[6];
  const float* img_adaln_b  = (const float*)d_in[7];
  const float* img_adaln_nw = (const float*)d_in[8];
  const float* txt_adaln_w  = (const float*)d_in[9];
  const float* txt_adaln_b  = (const float*)d_in[10];
  const float* txt_adaln_nw = (const float*)d_in[11];
  const float* txt_qkv_w    = (const float*)d_in[12];
  const float* img_qkv_w    = (const float*)d_in[13];
  const float* txt_out_w    = (const float*)d_in[14];
  const float* img_out_w    = (const float*)d_in[15];
  const float* sol_mod_w    = (const float*)d_in[16];
  const float* sol_mod_b    = (const float*)d_in[17];
  const float* img_norm2_w  = (const float*)d_in[18];
  const float* txt_norm2_w  = (const float*)d_in[19];
  const float* img_fc1_w    = (const float*)d_in[20];
  const float* img_fc1_b    = (const float*)d_in[21];
  const float* img_fc2_w    = (const float*)d_in[22];
  const float* img_fc2_b    = (const float*)d_in[23];
  const float* txt_fc1_w    = (const float*)d_in[24];
  const float* txt_fc1_b    = (const float*)d_in[25];
  const float* txt_fc2_w    = (const float*)d_in[26];
  const float* txt_fc2_b    = (const float*)d_in[27];
  float* out = (float*)d_out;

  GETSYM(e_img, d_e_img);  GETSYM(e_txt, d_e_txt);
  GETSYM(eff, d_eff);      GETSYM(mod, d_mod);
  GETSYM(nimg, d_nimg);    GETSYM(ntxt, d_ntxt);
  GETSYM(qkvi, d_qkvi);    GETSYM(qkvt, d_qkvt);
  GETSYM(Qi, d_Qi);        GETSYM(Qt, d_Qt);
  GETSYM(Kc, d_Kc);        GETSYM(VT, d_VT);
  GETSYM(St, d_St);        GETSYM(Si, d_Si);
  GETSYM(att_t, d_att_t);  GETSYM(att_i, d_att_i);
  GETSYM(apt, d_apt);      GETSYM(api, d_api);
  GETSYM(prt, d_prt);      GETSYM(pri, d_pri);
  GETSYM(ct, d_ct);        GETSYM(ci, d_ci);
  GETSYM(ht, d_ht);        GETSYM(hi, d_hi);

  cudaFuncSetAttribute(tgemm, cudaFuncAttributeMaxDynamicSharedMemorySize, TG_DSMEM);

  // 1. adaln embeddings
  k_emb<<<dim3(E6/256, NB), 256>>>(vec, img_adaln_w, img_adaln_b, e_img);
  k_emb<<<dim3(E6/256, NB), 256>>>(vec, txt_adaln_w, txt_adaln_b, e_txt);
  // 2. eff + mod
  k_eff<<<1, 32>>>(sol_t, eff);
  k_mod<<<(NB*NHD*NI)/256, 256>>>(sol_s, sol_mod_w, sol_mod_b, mod);
  // 3. norm1 (shift=sm@0, scale=cm@512)
  k_rmsmod<<<NB*NI, 128>>>(img, img_adaln_nw, e_img, 0, 512, nimg, NI);
  k_rmsmod<<<NB*LT, 128>>>(txt, txt_adaln_nw, e_txt, 0, 512, ntxt, LT);
  // 4. qkv projections
  tgemm<<<dim3(12, 32, 1), 256, TG_DSMEM>>>(nimg, img_qkv_w, qkvi, 1536, DM, 0,0,0, 1.f, nullptr, 1);
  tgemm<<<dim3(12,  8, 1), 256, TG_DSMEM>>>(ntxt, txt_qkv_w, qkvt, 1536, DM, 0,0,0, 1.f, nullptr, 1);
  // 5. scatter -> Q, K, V^T (rope + mod on img)
  k_scatter_img<<<(NB*NHD*NI*64)/256, 256>>>(qkvi, rope, mod, Qi, Kc, VT);
  k_scatter_txt<<<(NB*NHD*LT*64)/256, 256>>>(qkvt, Qt, Kc, VT);
  // 6. scores: S = alpha * Q @ K^T, batched over 8 (b,h)
  tgemm<<<dim3(KVL/128, LT/128, NB*NHD), 256, TG_DSMEM>>>(Qt, Kc, St, KVL, HDD,
      (long long)LT*HDD, (long long)KVL*HDD, (long long)LT*KVL, SCALE_C, nullptr, 1);
  tgemm<<<dim3(KVL/128, NI/128, NB*NHD), 256, TG_DSMEM>>>(Qi, Kc, Si, KVL, HDD,
      (long long)NI*HDD, (long long)KVL*HDD, (long long)NI*KVL, 1.f, eff, NHD);
  // 7. softmax
  k_softmax<<<NB*NHD*LT, 256>>>(St);
  k_softmax<<<NB*NHD*NI, 256>>>(Si);
  // 8. P @ V  (V stored transposed)
  tgemm<<<dim3(1, LT/128, NB*NHD), 256, TG_DSMEM>>>(St, VT, att_t, HDD, KVL,
      (long long)LT*KVL, (long long)HDD*KVL, (long long)LT*HDD, 1.f, nullptr, 1);
  tgemm<<<dim3(1, NI/128, NB*NHD), 256, TG_DSMEM>>>(Si, VT, att_i, HDD, KVL,
      (long long)NI*KVL, (long long)HDD*KVL, (long long)NI*HDD, 1.f, nullptr, 1);
  // 9. pack heads
  k_pack<<<(NB*LT*DM)/256, 256>>>(att_t, apt, LT);
  k_pack<<<(NB*NI*DM)/256, 256>>>(att_i, api, NI);
  // 10. output projections
  tgemm<<<dim3(4,  8, 1), 256, TG_DSMEM>>>(apt, txt_out_w, prt, DM, DM, 0,0,0, 1.f, nullptr, 1);
  tgemm<<<dim3(4, 32, 1), 256, TG_DSMEM>>>(api, img_out_w, pri, DM, DM, 0,0,0, 1.f, nullptr, 1);
  // 11. attention residual with gate gm@1024
  k_resgate<<<(NB*LT*DM)/256, 256>>>(txt, prt, e_txt, 1024, ct, LT);
  k_resgate<<<(NB*NI*DM)/256, 256>>>(img, pri, e_img, 1024, ci, NI);
  // 12. norm2 (shift=sp@1536, scale=cp@2048)
  k_rmsmod<<<NB*LT, 128>>>(ct, txt_norm2_w, e_txt, 1536, 2048, ntxt, LT);
  k_rmsmod<<<NB*NI, 128>>>(ci, img_norm2_w, e_img, 1536, 2048, nimg, NI);
  // 13. mlp fc1
  tgemm<<<dim3(16,  8, 1), 256, TG_DSMEM>>>(ntxt, txt_fc1_w, ht, FFD, DM, 0,0,0, 1.f, nullptr, 1);
  tgemm<<<dim3(16, 32, 1), 256, TG_DSMEM>>>(nimg, img_fc1_w, hi, FFD, DM, 0,0,0, 1.f, nullptr, 1);
  // 14. bias + gelu
  k_biasgelu<<<(NB*LT*FFD)/256, 256>>>(ht, txt_fc1_b, NB*LT*FFD);
  k_biasgelu<<<(NB*NI*FFD)/256, 256>>>(hi, img_fc1_b, NB*NI*FFD);
  // 15. mlp fc2 (reuse proj buffers)
  tgemm<<<dim3(4,  8, 1), 256, TG_DSMEM>>>(ht, txt_fc2_w, prt, DM, FFD, 0,0,0, 1.f, nullptr, 1);
  tgemm<<<dim3(4, 32, 1), 256, TG_DSMEM>>>(hi, img_fc2_w, pri, DM, FFD, 0,0,0, 1.f, nullptr, 1);
  // 16. final residual with gate gp@2560 (+fc2 bias) -> d_out (txt first, then img)
  k_final<<<(NB*LT*DM)/256, 256>>>(ct, prt, e_txt, txt_fc2_b, out, LT);
  k_final<<<(NB*NI*DM)/256, 256>>>(ci, pri, e_img, img_fc2_b, out + NB*LT*DM, NI);
}